// round 4
// baseline (speedup 1.0000x reference)
#include <cuda_runtime.h>
#include <cuda_bf16.h>
#include <cstdint>

// Problem constants
#define Bb 2
#define Tt 2048
#define Cc 1280
#define Hh 10
#define Dd 128
#define Mtot (Bb*Tt)          // 4096
#define SOFT_SCALE 0.08838834764831845f  // 1/sqrt(128)

// Scratch (device globals; allocation-free rule)
__device__ float g_q[Bb*Hh*Tt*Dd];
__device__ float g_k[Bb*Hh*Tt*Dd];
__device__ float g_v[Bb*Hh*Tt*Dd];
__device__ float g_att[Bb*Tt*Cc];   // attention output in [b,t,h,d] = [B,T,C]

// Split a float pair into packed bf16x2 hi and lo parts.
// x ~= hi + lo with ~16 mantissa bits of combined precision.
__device__ __forceinline__ void cvt_split_pair(float x, float y,
                                               uint32_t& hi, uint32_t& lo) {
    __nv_bfloat16 hx = __float2bfloat16_rn(x);
    __nv_bfloat16 hy = __float2bfloat16_rn(y);
    __nv_bfloat16 lx = __float2bfloat16_rn(x - __bfloat162float(hx));
    __nv_bfloat16 ly = __float2bfloat16_rn(y - __bfloat162float(hy));
    __nv_bfloat162 h; h.x = hx; h.y = hy;
    __nv_bfloat162 l; l.x = lx; l.y = ly;
    hi = *reinterpret_cast<uint32_t*>(&h);
    lo = *reinterpret_cast<uint32_t*>(&l);
}

#define BF16_MMA(d, a, b) \
    asm volatile( \
        "mma.sync.aligned.m16n8k16.row.col.f32.bf16.bf16.f32 " \
        "{%0,%1,%2,%3}, {%4,%5,%6,%7}, {%8,%9}, {%0,%1,%2,%3};\n" \
        : "+f"(d[0]), "+f"(d[1]), "+f"(d[2]), "+f"(d[3]) \
        : "r"(a[0]), "r"(a[1]), "r"(a[2]), "r"(a[3]), "r"(b[0]), "r"(b[1]))

// ---------------------------------------------------------------------------
// bf16 split-3 tensor-core GEMM: Out[m,n] = sum_k A[m,k] * W[n,k]
// Near-fp32 accuracy: D += Ah*Bh + Ah*Bl + Al*Bh  (lo*lo dropped, ~1.5e-5 rel)
// A: [4096,1280] row-major, W: [1280,1280] row-major (row.col mma)
// Block 128x128, BK=16 (8 b32 k-pairs), 256 threads = 8 warps (2m x 4n),
// warp tile 64x32 = 4x4 grid of m16n8k16.
// smem: b32-packed bf16 pairs, row stride 12 b32 (perfect 32-bank permutation
// for fragment loads: (gid*12 + tig) mod 32 covers all banks).
// mode 0: A<-g_att, write Out[m*1280+n] (proj)
// mode 1: grid.z picks Wq/Wk/Wv, writes to g_q/g_k/g_v in [b,h,t,d]
// ---------------------------------------------------------------------------
#define BK 16
#define BK32 8    // b32 (bf16x2) per k-row
#define SKB 12    // padded b32 stride

__global__ __launch_bounds__(256) void gemm_bf16s(
    const float* __restrict__ A,
    const float* __restrict__ W0,
    const float* __restrict__ W1,
    const float* __restrict__ W2,
    float* __restrict__ Out,
    int mode)
{
    __shared__ uint32_t Ah[2][128][SKB];
    __shared__ uint32_t Al[2][128][SKB];
    __shared__ uint32_t Bh[2][128][SKB];
    __shared__ uint32_t Bl[2][128][SKB];

    const float* Ain;
    const float* W;
    float* O;
    if (mode == 0) {
        Ain = g_att; W = W0; O = Out;
    } else {
        Ain = A;
        int z = blockIdx.z;
        W = (z == 0) ? W0 : ((z == 1) ? W1 : W2);
        O = (z == 0) ? g_q : ((z == 1) ? g_k : g_v);
    }

    const int tid  = threadIdx.x;
    const int warp = tid >> 5;
    const int lane = tid & 31;
    const int wm = warp & 1;       // 0..1
    const int wn = warp >> 1;      // 0..3
    const int gid = lane >> 2;     // 0..7
    const int tig = lane & 3;      // 0..3

    const int m0 = blockIdx.y * 128;
    const int n0 = blockIdx.x * 128;

    // gmem load mapping: thread covers rows (lr, lr+64), k-cols [lk, lk+4)
    const int lr  = tid >> 2;           // 0..63
    const int lk  = (tid & 3) << 2;     // 0,4,8,12 (floats)
    const int lk32 = lk >> 1;           // 0,2,4,6  (b32 pairs)

    const float* Aptr = Ain + (long)(m0 + lr) * Cc + lk;
    const float* Wptr = W   + (long)(n0 + lr) * Cc + lk;

    float acc[4][4][4];
#pragma unroll
    for (int mi = 0; mi < 4; mi++)
#pragma unroll
        for (int ni = 0; ni < 4; ni++)
#pragma unroll
            for (int c = 0; c < 4; c++) acc[mi][ni][c] = 0.f;

    const int NT = Cc / BK;   // 80 stages

    // Prologue: stage 0 -> smem buf 0
    {
        float4 ra0 = *(const float4*)(Aptr);
        float4 ra1 = *(const float4*)(Aptr + 64 * Cc);
        float4 rb0 = *(const float4*)(Wptr);
        float4 rb1 = *(const float4*)(Wptr + 64 * Cc);
        uint32_t h0, l0, h1, l1;
        cvt_split_pair(ra0.x, ra0.y, h0, l0); cvt_split_pair(ra0.z, ra0.w, h1, l1);
        Ah[0][lr][lk32] = h0; Ah[0][lr][lk32 + 1] = h1;
        Al[0][lr][lk32] = l0; Al[0][lr][lk32 + 1] = l1;
        cvt_split_pair(ra1.x, ra1.y, h0, l0); cvt_split_pair(ra1.z, ra1.w, h1, l1);
        Ah[0][lr + 64][lk32] = h0; Ah[0][lr + 64][lk32 + 1] = h1;
        Al[0][lr + 64][lk32] = l0; Al[0][lr + 64][lk32 + 1] = l1;
        cvt_split_pair(rb0.x, rb0.y, h0, l0); cvt_split_pair(rb0.z, rb0.w, h1, l1);
        Bh[0][lr][lk32] = h0; Bh[0][lr][lk32 + 1] = h1;
        Bl[0][lr][lk32] = l0; Bl[0][lr][lk32 + 1] = l1;
        cvt_split_pair(rb1.x, rb1.y, h0, l0); cvt_split_pair(rb1.z, rb1.w, h1, l1);
        Bh[0][lr + 64][lk32] = h0; Bh[0][lr + 64][lk32 + 1] = h1;
        Bl[0][lr + 64][lk32] = l0; Bl[0][lr + 64][lk32 + 1] = l1;
    }
    __syncthreads();

    int cur = 0;
    for (int t = 0; t < NT; ++t) {
        float4 ra0, ra1, rb0, rb1;
        const bool pf = (t + 1 < NT);
        if (pf) {
            int k0 = (t + 1) * BK;
            ra0 = *(const float4*)(Aptr + k0);
            ra1 = *(const float4*)(Aptr + 64 * Cc + k0);
            rb0 = *(const float4*)(Wptr + k0);
            rb1 = *(const float4*)(Wptr + 64 * Cc + k0);
        }

        // Compute one k16 step from smem[cur]: 3 mmas per (mi,ni)
        {
            uint32_t ah[4][4], al[4][4], bh[4][2], bl[4][2];
#pragma unroll
            for (int mi = 0; mi < 4; mi++) {
                int mr = wm * 64 + mi * 16 + gid;
                ah[mi][0] = Ah[cur][mr][tig];
                ah[mi][1] = Ah[cur][mr + 8][tig];
                ah[mi][2] = Ah[cur][mr][tig + 4];
                ah[mi][3] = Ah[cur][mr + 8][tig + 4];
                al[mi][0] = Al[cur][mr][tig];
                al[mi][1] = Al[cur][mr + 8][tig];
                al[mi][2] = Al[cur][mr][tig + 4];
                al[mi][3] = Al[cur][mr + 8][tig + 4];
            }
#pragma unroll
            for (int ni = 0; ni < 4; ni++) {
                int nc = wn * 32 + ni * 8 + gid;
                bh[ni][0] = Bh[cur][nc][tig];
                bh[ni][1] = Bh[cur][nc][tig + 4];
                bl[ni][0] = Bl[cur][nc][tig];
                bl[ni][1] = Bl[cur][nc][tig + 4];
            }
#pragma unroll
            for (int mi = 0; mi < 4; mi++)
#pragma unroll
                for (int ni = 0; ni < 4; ni++) {
                    BF16_MMA(acc[mi][ni], ah[mi], bh[ni]);
                    BF16_MMA(acc[mi][ni], ah[mi], bl[ni]);
                    BF16_MMA(acc[mi][ni], al[mi], bh[ni]);
                }
        }

        // Store prefetched stage into the other buffer
        if (pf) {
            int nb = cur ^ 1;
            uint32_t h0, l0, h1, l1;
            cvt_split_pair(ra0.x, ra0.y, h0, l0); cvt_split_pair(ra0.z, ra0.w, h1, l1);
            Ah[nb][lr][lk32] = h0; Ah[nb][lr][lk32 + 1] = h1;
            Al[nb][lr][lk32] = l0; Al[nb][lr][lk32 + 1] = l1;
            cvt_split_pair(ra1.x, ra1.y, h0, l0); cvt_split_pair(ra1.z, ra1.w, h1, l1);
            Ah[nb][lr + 64][lk32] = h0; Ah[nb][lr + 64][lk32 + 1] = h1;
            Al[nb][lr + 64][lk32] = l0; Al[nb][lr + 64][lk32 + 1] = l1;
            cvt_split_pair(rb0.x, rb0.y, h0, l0); cvt_split_pair(rb0.z, rb0.w, h1, l1);
            Bh[nb][lr][lk32] = h0; Bh[nb][lr][lk32 + 1] = h1;
            Bl[nb][lr][lk32] = l0; Bl[nb][lr][lk32 + 1] = l1;
            cvt_split_pair(rb1.x, rb1.y, h0, l0); cvt_split_pair(rb1.z, rb1.w, h1, l1);
            Bh[nb][lr + 64][lk32] = h0; Bh[nb][lr + 64][lk32 + 1] = h1;
            Bl[nb][lr + 64][lk32] = l0; Bl[nb][lr + 64][lk32 + 1] = l1;
        }
        __syncthreads();
        cur ^= 1;
    }

    // Epilogue: c0/c1 -> (row, 2*tig..+1), c2/c3 -> (row+8, same cols)
#pragma unroll
    for (int mi = 0; mi < 4; mi++) {
#pragma unroll
        for (int ni = 0; ni < 4; ni++) {
            int r_lo = m0 + wm * 64 + mi * 16 + gid;
            int cn = n0 + wn * 32 + ni * 8 + 2 * tig;
            float2 lo = make_float2(acc[mi][ni][0], acc[mi][ni][1]);
            float2 hi = make_float2(acc[mi][ni][2], acc[mi][ni][3]);
            if (mode == 0) {
                *(float2*)(O + (long)r_lo * Cc + cn)       = lo;
                *(float2*)(O + (long)(r_lo + 8) * Cc + cn) = hi;
            } else {
                int h_ = n0 >> 7;                 // N-tile == one head (128=D)
                int d_ = cn - n0;
                int b0_ = r_lo >> 11, t0_ = r_lo & (Tt - 1);
                int b1_ = (r_lo + 8) >> 11, t1_ = (r_lo + 8) & (Tt - 1);
                long base0 = ((long)(b0_ * Hh + h_) * Tt + t0_) * Dd + d_;
                long base1 = ((long)(b1_ * Hh + h_) * Tt + t1_) * Dd + d_;
                *(float2*)(O + base0) = lo;
                *(float2*)(O + base1) = hi;
            }
        }
    }
}

// ---------------------------------------------------------------------------
// Fused RoPE + RMSNorm on g_q / g_k, one warp per (b,h,t) row of 128.
// ---------------------------------------------------------------------------
__global__ __launch_bounds__(256) void rope_rms_kernel(
    const float* __restrict__ cosp, const float* __restrict__ sinp)
{
    int warp = threadIdx.x >> 5;
    int lane = threadIdx.x & 31;
    int row = blockIdx.x * 8 + warp;          // 0 .. B*H*T-1
    float* buf = (blockIdx.y == 0) ? g_q : g_k;
    int t = row & (Tt - 1);                   // row = (b*H+h)*T + t
    float* p = buf + (long)row * Dd;

    float x0 = p[lane], x1 = p[lane + 32], x2 = p[lane + 64], x3 = p[lane + 96];
    float c0 = cosp[t * 64 + lane], c1 = cosp[t * 64 + lane + 32];
    float s0 = sinp[t * 64 + lane], s1 = sinp[t * 64 + lane + 32];

    float y0 =  x0 * c0 + x2 * s0;
    float y2 = -x0 * s0 + x2 * c0;
    float y1 =  x1 * c1 + x3 * s1;
    float y3 = -x1 * s1 + x3 * c1;

    float ss = y0 * y0 + y1 * y1 + y2 * y2 + y3 * y3;
#pragma unroll
    for (int o = 16; o; o >>= 1) ss += __shfl_xor_sync(0xFFFFFFFFu, ss, o);
    float inv = rsqrtf(ss * (1.0f / 128.0f) + 1e-5f);

    p[lane]      = y0 * inv;
    p[lane + 32] = y1 * inv;
    p[lane + 64] = y2 * inv;
    p[lane + 96] = y3 * inv;
}

// ---------------------------------------------------------------------------
// Flash attention fp32 (unchanged): 64q x 64k tiles, D=128.
// ---------------------------------------------------------------------------
#define QS_STRIDE 132
#define KT_STRIDE 68
#define VS_STRIDE 132
#define PS_STRIDE 68
#define FLASH_SMEM_FLOATS (64*QS_STRIDE + 128*KT_STRIDE + 64*VS_STRIDE + 64*PS_STRIDE)

__global__ __launch_bounds__(256) void flash_kernel()
{
    extern __shared__ float sm[];
    float* Qs  = sm;                           // [64][132]
    float* Kst = Qs + 64 * QS_STRIDE;          // [128][68]  (d-major)
    float* Vs  = Kst + 128 * KT_STRIDE;        // [64][132]
    float* Ps  = Vs + 64 * VS_STRIDE;          // [64][68]

    const int tid = threadIdx.x;
    const int ty = tid >> 4;
    const int tx = tid & 15;
    const int r0 = ty << 2;
    const int c0 = tx << 2;

    const int qtile = gridDim.x - 1 - blockIdx.x;   // heavy tiles first
    const int bh = blockIdx.y;
    const int b_ = bh / Hh, h_ = bh % Hh;
    const long hdbase = (long)(b_ * Hh + h_) * Tt * Dd;
    const float* qb = g_q + hdbase;
    const float* kb = g_k + hdbase;
    const float* vb = g_v + hdbase;
    const int qbase = qtile * 64;

    // Load + pre-scale Q tile
    for (int idx = tid; idx < 64 * 32; idx += 256) {
        int r = idx >> 5, c4 = (idx & 31) << 2;
        float4 v = *(const float4*)(qb + (long)(qbase + r) * Dd + c4);
        float* dst = Qs + r * QS_STRIDE + c4;
        dst[0] = v.x * SOFT_SCALE; dst[1] = v.y * SOFT_SCALE;
        dst[2] = v.z * SOFT_SCALE; dst[3] = v.w * SOFT_SCALE;
    }

    float m_i[4], l_i[4], o[4][8];
#pragma unroll
    for (int i = 0; i < 4; i++) {
        m_i[i] = -1e30f; l_i[i] = 0.f;
#pragma unroll
        for (int c = 0; c < 8; c++) o[i][c] = 0.f;
    }

    for (int kt = 0; kt <= qtile; kt++) {
        __syncthreads();
        const int kbase = kt * 64;

        for (int idx = tid; idx < 64 * 32; idx += 256) {
            int key = idx >> 5, d4 = (idx & 31) << 2;
            float4 kv = *(const float4*)(kb + (long)(kbase + key) * Dd + d4);
            Kst[(d4 + 0) * KT_STRIDE + key] = kv.x;
            Kst[(d4 + 1) * KT_STRIDE + key] = kv.y;
            Kst[(d4 + 2) * KT_STRIDE + key] = kv.z;
            Kst[(d4 + 3) * KT_STRIDE + key] = kv.w;
            float4 vv = *(const float4*)(vb + (long)(kbase + key) * Dd + d4);
            *(float4*)(Vs + key * VS_STRIDE + d4) = vv;
        }
        __syncthreads();

        float s[4][4];
#pragma unroll
        for (int i = 0; i < 4; i++)
#pragma unroll
            for (int j = 0; j < 4; j++) s[i][j] = 0.f;

#pragma unroll 4
        for (int d4 = 0; d4 < 32; d4++) {
            float4 q[4];
#pragma unroll
            for (int i = 0; i < 4; i++)
                q[i] = *(const float4*)(Qs + (r0 + i) * QS_STRIDE + (d4 << 2));
            float4 k0 = *(const float4*)(Kst + (d4 * 4 + 0) * KT_STRIDE + c0);
            float4 k1 = *(const float4*)(Kst + (d4 * 4 + 1) * KT_STRIDE + c0);
            float4 k2 = *(const float4*)(Kst + (d4 * 4 + 2) * KT_STRIDE + c0);
            float4 k3 = *(const float4*)(Kst + (d4 * 4 + 3) * KT_STRIDE + c0);
#pragma unroll
            for (int i = 0; i < 4; i++) {
                s[i][0] += q[i].x * k0.x; s[i][1] += q[i].x * k0.y;
                s[i][2] += q[i].x * k0.z; s[i][3] += q[i].x * k0.w;
                s[i][0] += q[i].y * k1.x; s[i][1] += q[i].y * k1.y;
                s[i][2] += q[i].y * k1.z; s[i][3] += q[i].y * k1.w;
                s[i][0] += q[i].z * k2.x; s[i][1] += q[i].z * k2.y;
                s[i][2] += q[i].z * k2.z; s[i][3] += q[i].z * k2.w;
                s[i][0] += q[i].w * k3.x; s[i][1] += q[i].w * k3.y;
                s[i][2] += q[i].w * k3.z; s[i][3] += q[i].w * k3.w;
            }
        }

        if (kt == qtile) {
#pragma unroll
            for (int i = 0; i < 4; i++)
#pragma unroll
                for (int j = 0; j < 4; j++)
                    if (kbase + c0 + j > qbase + r0 + i) s[i][j] = -1e30f;
        }

#pragma unroll
        for (int i = 0; i < 4; i++) {
            float mx = fmaxf(fmaxf(s[i][0], s[i][1]), fmaxf(s[i][2], s[i][3]));
#pragma unroll
            for (int off = 1; off < 16; off <<= 1)
                mx = fmaxf(mx, __shfl_xor_sync(0xFFFFFFFFu, mx, off));
            float mn = fmaxf(m_i[i], mx);
            float alpha = __expf(m_i[i] - mn);
            float rs = 0.f;
#pragma unroll
            for (int j = 0; j < 4; j++) {
                float p = __expf(s[i][j] - mn);
                s[i][j] = p;
                rs += p;
            }
#pragma unroll
            for (int off = 1; off < 16; off <<= 1)
                rs += __shfl_xor_sync(0xFFFFFFFFu, rs, off);
            l_i[i] = l_i[i] * alpha + rs;
            m_i[i] = mn;
#pragma unroll
            for (int c = 0; c < 8; c++) o[i][c] *= alpha;
#pragma unroll
            for (int j = 0; j < 4; j++)
                Ps[(r0 + i) * PS_STRIDE + c0 + j] = s[i][j];
        }
        __syncthreads();

#pragma unroll 4
        for (int j = 0; j < 64; j++) {
            float p0 = Ps[(r0 + 0) * PS_STRIDE + j];
            float p1 = Ps[(r0 + 1) * PS_STRIDE + j];
            float p2 = Ps[(r0 + 2) * PS_STRIDE + j];
            float p3 = Ps[(r0 + 3) * PS_STRIDE + j];
            float4 va = *(const float4*)(Vs + j * VS_STRIDE + (tx << 2));
            float4 vb4 = *(const float4*)(Vs + j * VS_STRIDE + 64 + (tx << 2));
            o[0][0] += p0 * va.x;  o[0][1] += p0 * va.y;  o[0][2] += p0 * va.z;  o[0][3] += p0 * va.w;
            o[0][4] += p0 * vb4.x; o[0][5] += p0 * vb4.y; o[0][6] += p0 * vb4.z; o[0][7] += p0 * vb4.w;
            o[1][0] += p1 * va.x;  o[1][1] += p1 * va.y;  o[1][2] += p1 * va.z;  o[1][3] += p1 * va.w;
            o[1][4] += p1 * vb4.x; o[1][5] += p1 * vb4.y; o[1][6] += p1 * vb4.z; o[1][7] += p1 * vb4.w;
            o[2][0] += p2 * va.x;  o[2][1] += p2 * va.y;  o[2][2] += p2 * va.z;  o[2][3] += p2 * va.w;
            o[2][4] += p2 * vb4.x; o[2][5] += p2 * vb4.y; o[2][6] += p2 * vb4.z; o[2][7] += p2 * vb4.w;
            o[3][0] += p3 * va.x;  o[3][1] += p3 * va.y;  o[3][2] += p3 * va.z;  o[3][3] += p3 * va.w;
            o[3][4] += p3 * vb4.x; o[3][5] += p3 * vb4.y; o[3][6] += p3 * vb4.z; o[3][7] += p3 * vb4.w;
        }
    }

#pragma unroll
    for (int i = 0; i < 4; i++) {
        float invl = 1.0f / l_i[i];
        int t_ = qbase + r0 + i;
        long base = (long)(b_ * Tt + t_) * Cc + h_ * Dd;
        float4 w0 = make_float4(o[i][0] * invl, o[i][1] * invl, o[i][2] * invl, o[i][3] * invl);
        float4 w1 = make_float4(o[i][4] * invl, o[i][5] * invl, o[i][6] * invl, o[i][7] * invl);
        *(float4*)(g_att + base + (tx << 2))      = w0;
        *(float4*)(g_att + base + 64 + (tx << 2)) = w1;
    }
}

// ---------------------------------------------------------------------------
extern "C" void kernel_launch(void* const* d_in, const int* in_sizes, int n_in,
                              void* d_out, int out_size)
{
    const float* x    = (const float*)d_in[0];
    const float* cosp = (const float*)d_in[1];
    const float* sinp = (const float*)d_in[2];
    const float* Wq   = (const float*)d_in[3];
    const float* Wk   = (const float*)d_in[4];
    const float* Wv   = (const float*)d_in[5];
    const float* Wp   = (const float*)d_in[6];
    float* out = (float*)d_out;

    const int flash_smem = FLASH_SMEM_FLOATS * (int)sizeof(float);
    cudaFuncSetAttribute(flash_kernel,
                         cudaFuncAttributeMaxDynamicSharedMemorySize, flash_smem);

    // 1) Q/K/V projections (bf16 split-3 tensor cores, ~fp32 accuracy)
    gemm_bf16s<<<dim3(Cc / 128, Mtot / 128, 3), 256>>>(x, Wq, Wk, Wv, nullptr, 1);
    // 2) RoPE + RMSNorm on q and k
    rope_rms_kernel<<<dim3((Bb * Hh * Tt) / 8, 2), 256>>>(cosp, sinp);
    // 3) Flash attention (fp32)
    flash_kernel<<<dim3(Tt / 64, Bb * Hh), 256, flash_smem>>>();
    // 4) Output projection (bf16 split-3 tensor cores)
    gemm_bf16s<<<dim3(Cc / 128, Mtot / 128, 1), 256>>>(nullptr, Wp, nullptr, nullptr, out, 0);
}

// round 5
// speedup vs baseline: 1.6321x; 1.6321x over previous
#include <cuda_runtime.h>
#include <cuda_bf16.h>
#include <cstdint>

// Problem constants
#define Bb 2
#define Tt 2048
#define Cc 1280
#define Hh 10
#define Dd 128
#define Mtot (Bb*Tt)          // 4096
#define SOFT_SCALE 0.08838834764831845f  // 1/sqrt(128)

// Scratch (device globals; allocation-free rule)
__device__ float g_q[Bb*Hh*Tt*Dd];
__device__ float g_k[Bb*Hh*Tt*Dd];
__device__ float g_v[Bb*Hh*Tt*Dd];
__device__ float g_att[Bb*Tt*Cc];   // attention output in [b,t,h,d] = [B,T,C]

__device__ __forceinline__ float to_tf32(float x) {
    float r;
    asm("cvt.rna.tf32.f32 %0, %1;" : "=f"(r) : "f"(x));
    return r;
}

// Split a float pair into packed bf16x2 hi and lo parts (x->low16, y->high16).
__device__ __forceinline__ void cvt_split_pair(float x, float y,
                                               uint32_t& hi, uint32_t& lo) {
    __nv_bfloat16 hx = __float2bfloat16_rn(x);
    __nv_bfloat16 hy = __float2bfloat16_rn(y);
    __nv_bfloat16 lx = __float2bfloat16_rn(x - __bfloat162float(hx));
    __nv_bfloat16 ly = __float2bfloat16_rn(y - __bfloat162float(hy));
    __nv_bfloat162 h; h.x = hx; h.y = hy;
    __nv_bfloat162 l; l.x = lx; l.y = ly;
    hi = *reinterpret_cast<uint32_t*>(&h);
    lo = *reinterpret_cast<uint32_t*>(&l);
}

#define BF16_MMA(d, a, b) \
    asm volatile( \
        "mma.sync.aligned.m16n8k16.row.col.f32.bf16.bf16.f32 " \
        "{%0,%1,%2,%3}, {%4,%5,%6,%7}, {%8,%9}, {%0,%1,%2,%3};\n" \
        : "+f"(d[0]), "+f"(d[1]), "+f"(d[2]), "+f"(d[3]) \
        : "r"(a[0]), "r"(a[1]), "r"(a[2]), "r"(a[3]), "r"(b[0]), "r"(b[1]))

// ---------------------------------------------------------------------------
// TF32 tensor-core SGEMM (R3, known good): Out[m,n] = sum_k A[m,k] * W[n,k]
// ---------------------------------------------------------------------------
#define BK 16
#define SK 20   // padded k-stride

__global__ __launch_bounds__(256) void gemm_tf32(
    const float* __restrict__ A,
    const float* __restrict__ W0,
    const float* __restrict__ W1,
    const float* __restrict__ W2,
    float* __restrict__ Out,
    int mode)
{
    __shared__ float As[2][128][SK];
    __shared__ float Bs[2][128][SK];

    const float* Ain;
    const float* W;
    float* O;
    if (mode == 0) {
        Ain = g_att; W = W0; O = Out;
    } else {
        Ain = A;
        int z = blockIdx.z;
        W = (z == 0) ? W0 : ((z == 1) ? W1 : W2);
        O = (z == 0) ? g_q : ((z == 1) ? g_k : g_v);
    }

    const int tid  = threadIdx.x;
    const int warp = tid >> 5;
    const int lane = tid & 31;
    const int wm = warp & 1;
    const int wn = warp >> 1;
    const int gid = lane >> 2;
    const int tig = lane & 3;

    const int m0 = blockIdx.y * 128;
    const int n0 = blockIdx.x * 128;

    const int lr = tid >> 2;
    const int lk = (tid & 3) << 2;

    const float* Aptr = Ain + (long)(m0 + lr) * Cc + lk;
    const float* Wptr = W   + (long)(n0 + lr) * Cc + lk;

    float acc[4][4][4];
#pragma unroll
    for (int mi = 0; mi < 4; mi++)
#pragma unroll
        for (int ni = 0; ni < 4; ni++)
#pragma unroll
            for (int c = 0; c < 4; c++) acc[mi][ni][c] = 0.f;

    const int NT = Cc / BK;

    {
        float4 ra0 = *(const float4*)(Aptr);
        float4 ra1 = *(const float4*)(Aptr + 64 * Cc);
        float4 rb0 = *(const float4*)(Wptr);
        float4 rb1 = *(const float4*)(Wptr + 64 * Cc);
        float* pa0 = &As[0][lr][lk];
        float* pa1 = &As[0][lr + 64][lk];
        float* pb0 = &Bs[0][lr][lk];
        float* pb1 = &Bs[0][lr + 64][lk];
        pa0[0] = to_tf32(ra0.x); pa0[1] = to_tf32(ra0.y); pa0[2] = to_tf32(ra0.z); pa0[3] = to_tf32(ra0.w);
        pa1[0] = to_tf32(ra1.x); pa1[1] = to_tf32(ra1.y); pa1[2] = to_tf32(ra1.z); pa1[3] = to_tf32(ra1.w);
        pb0[0] = to_tf32(rb0.x); pb0[1] = to_tf32(rb0.y); pb0[2] = to_tf32(rb0.z); pb0[3] = to_tf32(rb0.w);
        pb1[0] = to_tf32(rb1.x); pb1[1] = to_tf32(rb1.y); pb1[2] = to_tf32(rb1.z); pb1[3] = to_tf32(rb1.w);
    }
    __syncthreads();

    int cur = 0;
    for (int t = 0; t < NT; ++t) {
        float4 ra0, ra1, rb0, rb1;
        const bool pf = (t + 1 < NT);
        if (pf) {
            int k0 = (t + 1) * BK;
            ra0 = *(const float4*)(Aptr + k0);
            ra1 = *(const float4*)(Aptr + 64 * Cc + k0);
            rb0 = *(const float4*)(Wptr + k0);
            rb1 = *(const float4*)(Wptr + 64 * Cc + k0);
        }

#pragma unroll
        for (int kk = 0; kk < BK; kk += 8) {
            uint32_t a[4][4], b[4][2];
#pragma unroll
            for (int mi = 0; mi < 4; mi++) {
                int mr = wm * 64 + mi * 16 + gid;
                a[mi][0] = __float_as_uint(As[cur][mr][kk + tig]);
                a[mi][1] = __float_as_uint(As[cur][mr + 8][kk + tig]);
                a[mi][2] = __float_as_uint(As[cur][mr][kk + tig + 4]);
                a[mi][3] = __float_as_uint(As[cur][mr + 8][kk + tig + 4]);
            }
#pragma unroll
            for (int ni = 0; ni < 4; ni++) {
                int nc = wn * 32 + ni * 8 + gid;
                b[ni][0] = __float_as_uint(Bs[cur][nc][kk + tig]);
                b[ni][1] = __float_as_uint(Bs[cur][nc][kk + tig + 4]);
            }
#pragma unroll
            for (int mi = 0; mi < 4; mi++)
#pragma unroll
                for (int ni = 0; ni < 4; ni++) {
                    asm volatile(
                        "mma.sync.aligned.m16n8k8.row.col.f32.tf32.tf32.f32 "
                        "{%0,%1,%2,%3}, {%4,%5,%6,%7}, {%8,%9}, {%0,%1,%2,%3};\n"
                        : "+f"(acc[mi][ni][0]), "+f"(acc[mi][ni][1]),
                          "+f"(acc[mi][ni][2]), "+f"(acc[mi][ni][3])
                        : "r"(a[mi][0]), "r"(a[mi][1]), "r"(a[mi][2]), "r"(a[mi][3]),
                          "r"(b[ni][0]), "r"(b[ni][1]));
                }
        }

        if (pf) {
            int nb = cur ^ 1;
            float* pa0 = &As[nb][lr][lk];
            float* pa1 = &As[nb][lr + 64][lk];
            float* pb0 = &Bs[nb][lr][lk];
            float* pb1 = &Bs[nb][lr + 64][lk];
            pa0[0] = to_tf32(ra0.x); pa0[1] = to_tf32(ra0.y); pa0[2] = to_tf32(ra0.z); pa0[3] = to_tf32(ra0.w);
            pa1[0] = to_tf32(ra1.x); pa1[1] = to_tf32(ra1.y); pa1[2] = to_tf32(ra1.z); pa1[3] = to_tf32(ra1.w);
            pb0[0] = to_tf32(rb0.x); pb0[1] = to_tf32(rb0.y); pb0[2] = to_tf32(rb0.z); pb0[3] = to_tf32(rb0.w);
            pb1[0] = to_tf32(rb1.x); pb1[1] = to_tf32(rb1.y); pb1[2] = to_tf32(rb1.z); pb1[3] = to_tf32(rb1.w);
        }
        __syncthreads();
        cur ^= 1;
    }

#pragma unroll
    for (int mi = 0; mi < 4; mi++) {
#pragma unroll
        for (int ni = 0; ni < 4; ni++) {
            int r_lo = m0 + wm * 64 + mi * 16 + gid;
            int cn = n0 + wn * 32 + ni * 8 + 2 * tig;
            float2 lo = make_float2(acc[mi][ni][0], acc[mi][ni][1]);
            float2 hi = make_float2(acc[mi][ni][2], acc[mi][ni][3]);
            if (mode == 0) {
                *(float2*)(O + (long)r_lo * Cc + cn)       = lo;
                *(float2*)(O + (long)(r_lo + 8) * Cc + cn) = hi;
            } else {
                int h_ = n0 >> 7;
                int d_ = cn - n0;
                int b0_ = r_lo >> 11, t0_ = r_lo & (Tt - 1);
                int b1_ = (r_lo + 8) >> 11, t1_ = (r_lo + 8) & (Tt - 1);
                long base0 = ((long)(b0_ * Hh + h_) * Tt + t0_) * Dd + d_;
                long base1 = ((long)(b1_ * Hh + h_) * Tt + t1_) * Dd + d_;
                *(float2*)(O + base0) = lo;
                *(float2*)(O + base1) = hi;
            }
        }
    }
}

// ---------------------------------------------------------------------------
// Fused RoPE + RMSNorm on g_q / g_k, one warp per (b,h,t) row of 128.
// ---------------------------------------------------------------------------
__global__ __launch_bounds__(256) void rope_rms_kernel(
    const float* __restrict__ cosp, const float* __restrict__ sinp)
{
    int warp = threadIdx.x >> 5;
    int lane = threadIdx.x & 31;
    int row = blockIdx.x * 8 + warp;
    float* buf = (blockIdx.y == 0) ? g_q : g_k;
    int t = row & (Tt - 1);
    float* p = buf + (long)row * Dd;

    float x0 = p[lane], x1 = p[lane + 32], x2 = p[lane + 64], x3 = p[lane + 96];
    float c0 = cosp[t * 64 + lane], c1 = cosp[t * 64 + lane + 32];
    float s0 = sinp[t * 64 + lane], s1 = sinp[t * 64 + lane + 32];

    float y0 =  x0 * c0 + x2 * s0;
    float y2 = -x0 * s0 + x2 * c0;
    float y1 =  x1 * c1 + x3 * s1;
    float y3 = -x1 * s1 + x3 * c1;

    float ss = y0 * y0 + y1 * y1 + y2 * y2 + y3 * y3;
#pragma unroll
    for (int o = 16; o; o >>= 1) ss += __shfl_xor_sync(0xFFFFFFFFu, ss, o);
    float inv = rsqrtf(ss * (1.0f / 128.0f) + 1e-5f);

    p[lane]      = y0 * inv;
    p[lane + 32] = y1 * inv;
    p[lane + 64] = y2 * inv;
    p[lane + 96] = y3 * inv;
}

// ---------------------------------------------------------------------------
// Flash attention, bf16 split-3 tensor cores. Br=128 q-rows/block, Bc=64 keys
// per tile, 8 warps: warp w owns q-rows [w*16, w*16+16) (one m16 tile).
// S = Q K^T via 8 n8-tiles x 8 k16-steps, 3 mmas each (hi*hi+hi*lo+lo*hi).
// Softmax on S fragments (quad shfl rows). P fragments re-split in registers
// and fed straight into PV mma (FA2 layout identity) against Vt (d-major).
// Error contribution ~1e-5 (split-3), so total stays at the TF32-GEMM floor.
// ---------------------------------------------------------------------------
#define FQP 68   // Q pair-stride (64 pairs + 4 pad)
#define FKP 68
#define FVP 36   // Vt pair-stride over keys (32 pairs + 4 pad)
#define FLASH_SMEM_BYTES ((2*128*FQP + 2*64*FKP + 2*128*FVP) * 4)

__global__ __launch_bounds__(256) void flash_mma_kernel()
{
    extern __shared__ uint32_t smu[];
    uint32_t* Qh = smu;                  // [128][FQP]
    uint32_t* Ql = Qh + 128 * FQP;
    uint32_t* Kh = Ql + 128 * FQP;       // [64][FKP]
    uint32_t* Kl = Kh + 64 * FKP;
    uint32_t* Vh = Kl + 64 * FKP;        // [128][FVP] (d-major, keys packed)
    uint32_t* Vl = Vh + 128 * FVP;

    const int tid  = threadIdx.x;
    const int wid  = tid >> 5;
    const int lane = tid & 31;
    const int gid  = lane >> 2;   // 0..7
    const int tig  = lane & 3;    // 0..3

    const int qtile = gridDim.x - 1 - blockIdx.x;   // heavy tiles first
    const int bh = blockIdx.y;
    const int b_ = bh / Hh, h_ = bh % Hh;
    const long base = (long)bh * Tt * Dd;
    const float* qb = g_q + base;
    const float* kb = g_k + base;
    const float* vb = g_v + base;
    const int qb0 = qtile * 128;

    // Load + scale + split Q tile [128][128]
    for (int i = tid; i < 128 * 32; i += 256) {
        int r = i >> 5, f4 = i & 31;
        float4 v = *(const float4*)(qb + (long)(qb0 + r) * Dd + f4 * 4);
        uint32_t h0, l0, h1, l1;
        cvt_split_pair(v.x * SOFT_SCALE, v.y * SOFT_SCALE, h0, l0);
        cvt_split_pair(v.z * SOFT_SCALE, v.w * SOFT_SCALE, h1, l1);
        Qh[r * FQP + 2 * f4]     = h0; Qh[r * FQP + 2 * f4 + 1] = h1;
        Ql[r * FQP + 2 * f4]     = l0; Ql[r * FQP + 2 * f4 + 1] = l1;
    }

    float o[16][4];
    float m_[2], l_[2];
#pragma unroll
    for (int ni = 0; ni < 16; ni++)
#pragma unroll
        for (int c = 0; c < 4; c++) o[ni][c] = 0.f;
    m_[0] = m_[1] = -1e30f;
    l_[0] = l_[1] = 0.f;

    const int qrow = wid * 16;
    const int ktmax = 2 * qtile + 2;

    for (int kt = 0; kt < ktmax; kt++) {
        __syncthreads();   // previous iter's smem reads done / Q stores visible
        const int kbase = kt * 64;

        // Load + split K tile [64][128]
        for (int i = tid; i < 64 * 32; i += 256) {
            int r = i >> 5, f4 = i & 31;
            float4 v = *(const float4*)(kb + (long)(kbase + r) * Dd + f4 * 4);
            uint32_t h0, l0, h1, l1;
            cvt_split_pair(v.x, v.y, h0, l0);
            cvt_split_pair(v.z, v.w, h1, l1);
            Kh[r * FKP + 2 * f4]     = h0; Kh[r * FKP + 2 * f4 + 1] = h1;
            Kl[r * FKP + 2 * f4]     = l0; Kl[r * FKP + 2 * f4 + 1] = l1;
        }
        // Load + transpose + split V tile -> Vt[d][keypair]
        for (int i = tid; i < 128 * 32; i += 256) {
            int d = i & 127, kp = i >> 7;
            float v0 = vb[(long)(kbase + 2 * kp) * Dd + d];
            float v1 = vb[(long)(kbase + 2 * kp + 1) * Dd + d];
            uint32_t h, l;
            cvt_split_pair(v0, v1, h, l);
            Vh[d * FVP + kp] = h;
            Vl[d * FVP + kp] = l;
        }
        __syncthreads();

        // ---- S = Q K^T (warp: m16 x n64, k=128) ----
        float s[8][4];
#pragma unroll
        for (int t = 0; t < 8; t++)
#pragma unroll
            for (int c = 0; c < 4; c++) s[t][c] = 0.f;

#pragma unroll
        for (int j = 0; j < 8; j++) {
            uint32_t ah[4], al[4];
            ah[0] = Qh[(qrow + gid) * FQP + 8 * j + tig];
            ah[1] = Qh[(qrow + gid + 8) * FQP + 8 * j + tig];
            ah[2] = Qh[(qrow + gid) * FQP + 8 * j + tig + 4];
            ah[3] = Qh[(qrow + gid + 8) * FQP + 8 * j + tig + 4];
            al[0] = Ql[(qrow + gid) * FQP + 8 * j + tig];
            al[1] = Ql[(qrow + gid + 8) * FQP + 8 * j + tig];
            al[2] = Ql[(qrow + gid) * FQP + 8 * j + tig + 4];
            al[3] = Ql[(qrow + gid + 8) * FQP + 8 * j + tig + 4];
#pragma unroll
            for (int ni = 0; ni < 8; ni++) {
                uint32_t bh[2], bl[2];
                bh[0] = Kh[(8 * ni + gid) * FKP + 8 * j + tig];
                bh[1] = Kh[(8 * ni + gid) * FKP + 8 * j + tig + 4];
                bl[0] = Kl[(8 * ni + gid) * FKP + 8 * j + tig];
                bl[1] = Kl[(8 * ni + gid) * FKP + 8 * j + tig + 4];
                BF16_MMA(s[ni], ah, bh);
                BF16_MMA(s[ni], ah, bl);
                BF16_MMA(s[ni], al, bh);
            }
        }

        // ---- causal mask (only the two diagonal-adjacent k-tiles) ----
        if (kt >= 2 * qtile) {
            int r0g = qb0 + qrow + gid;
#pragma unroll
            for (int t = 0; t < 8; t++) {
                int col = kbase + 8 * t + 2 * tig;
                if (col     > r0g)     s[t][0] = -1e30f;
                if (col + 1 > r0g)     s[t][1] = -1e30f;
                if (col     > r0g + 8) s[t][2] = -1e30f;
                if (col + 1 > r0g + 8) s[t][3] = -1e30f;
            }
        }

        // ---- online softmax (rows gid, gid+8; quad reduce over tig) ----
#pragma unroll
        for (int r = 0; r < 2; r++) {
            float mx = -1e30f;
#pragma unroll
            for (int t = 0; t < 8; t++)
                mx = fmaxf(mx, fmaxf(s[t][2 * r], s[t][2 * r + 1]));
            mx = fmaxf(mx, __shfl_xor_sync(0xFFFFFFFFu, mx, 1));
            mx = fmaxf(mx, __shfl_xor_sync(0xFFFFFFFFu, mx, 2));
            float mn = fmaxf(m_[r], mx);
            float alpha = __expf(m_[r] - mn);
            float sum = 0.f;
#pragma unroll
            for (int t = 0; t < 8; t++) {
                float p0 = __expf(s[t][2 * r]     - mn);
                float p1 = __expf(s[t][2 * r + 1] - mn);
                s[t][2 * r] = p0; s[t][2 * r + 1] = p1;
                sum += p0 + p1;
            }
            sum += __shfl_xor_sync(0xFFFFFFFFu, sum, 1);
            sum += __shfl_xor_sync(0xFFFFFFFFu, sum, 2);
            l_[r] = l_[r] * alpha + sum;
            m_[r] = mn;
#pragma unroll
            for (int ni = 0; ni < 16; ni++) {
                o[ni][2 * r]     *= alpha;
                o[ni][2 * r + 1] *= alpha;
            }
        }

        // ---- O += P V  (P split in registers; V from smem d-major) ----
#pragma unroll
        for (int j = 0; j < 4; j++) {
            uint32_t ah[4], al[4];
            cvt_split_pair(s[2 * j][0],     s[2 * j][1],     ah[0], al[0]);
            cvt_split_pair(s[2 * j][2],     s[2 * j][3],     ah[1], al[1]);
            cvt_split_pair(s[2 * j + 1][0], s[2 * j + 1][1], ah[2], al[2]);
            cvt_split_pair(s[2 * j + 1][2], s[2 * j + 1][3], ah[3], al[3]);
#pragma unroll
            for (int ni = 0; ni < 16; ni++) {
                uint32_t bh[2], bl[2];
                bh[0] = Vh[(8 * ni + gid) * FVP + 8 * j + tig];
                bh[1] = Vh[(8 * ni + gid) * FVP + 8 * j + tig + 4];
                bl[0] = Vl[(8 * ni + gid) * FVP + 8 * j + tig];
                bl[1] = Vl[(8 * ni + gid) * FVP + 8 * j + tig + 4];
                BF16_MMA(o[ni], ah, bh);
                BF16_MMA(o[ni], ah, bl);
                BF16_MMA(o[ni], al, bh);
            }
        }
    }

    // ---- epilogue: normalize, write g_att [b,t,h,d] ----
    float inv0 = 1.f / l_[0];
    float inv1 = 1.f / l_[1];
    int r0g = qb0 + qrow + gid;
    long ob0 = ((long)(b_ * Tt + r0g))     * Cc + h_ * Dd;
    long ob1 = ((long)(b_ * Tt + r0g + 8)) * Cc + h_ * Dd;
#pragma unroll
    for (int ni = 0; ni < 16; ni++) {
        int d = 8 * ni + 2 * tig;
        *(float2*)(g_att + ob0 + d) = make_float2(o[ni][0] * inv0, o[ni][1] * inv0);
        *(float2*)(g_att + ob1 + d) = make_float2(o[ni][2] * inv1, o[ni][3] * inv1);
    }
}

// ---------------------------------------------------------------------------
extern "C" void kernel_launch(void* const* d_in, const int* in_sizes, int n_in,
                              void* d_out, int out_size)
{
    const float* x    = (const float*)d_in[0];
    const float* cosp = (const float*)d_in[1];
    const float* sinp = (const float*)d_in[2];
    const float* Wq   = (const float*)d_in[3];
    const float* Wk   = (const float*)d_in[4];
    const float* Wv   = (const float*)d_in[5];
    const float* Wp   = (const float*)d_in[6];
    float* out = (float*)d_out;

    cudaFuncSetAttribute(flash_mma_kernel,
                         cudaFuncAttributeMaxDynamicSharedMemorySize,
                         FLASH_SMEM_BYTES);

    // 1) Q/K/V projections (TF32 tensor cores)
    gemm_tf32<<<dim3(Cc / 128, Mtot / 128, 3), 256>>>(x, Wq, Wk, Wv, nullptr, 1);
    // 2) RoPE + RMSNorm on q and k
    rope_rms_kernel<<<dim3((Bb * Hh * Tt) / 8, 2), 256>>>(cosp, sinp);
    // 3) Flash attention (bf16 split-3 tensor cores)
    flash_mma_kernel<<<dim3(Tt / 128, Bb * Hh), 256, FLASH_SMEM_BYTES>>>();
    // 4) Output projection (TF32 tensor cores)
    gemm_tf32<<<dim3(Cc / 128, Mtot / 128, 1), 256>>>(nullptr, Wp, nullptr, nullptr, out, 0);
}